// round 16
// baseline (speedup 1.0000x reference)
#include <cuda_runtime.h>
#include <cuda_fp16.h>
#include <cstdint>

#define NB   16
#define SQ   4096
#define SKV  4096
#define HD   64

// ---------------- fp16 staging buffers ----------------
__device__ __half g_qh[(size_t)NB * SQ * HD];    // Q * 0.125*log2e
__device__ __half g_kh[(size_t)NB * SKV * HD];   // K
__device__ __half g_vh[(size_t)NB * SKV * HD];   // V
__device__ __half g_mh[(size_t)SQ * SKV];        // mask * log2e

// ---------------- fused conversion pre-pass ----------------
#define N4Q (NB * SQ * HD / 4)
#define N4M (SQ * SKV / 4)
__global__ void cvt_all(const float* __restrict__ q, const float* __restrict__ k,
                        const float* __restrict__ v, const float* __restrict__ m) {
    int i = blockIdx.x * blockDim.x + threadIdx.x;
    const float* src;
    __half* dst;
    float scale;
    if (i < N4Q)              { src = q; dst = g_qh; scale = 0.18033688011112042f; }
    else if (i < 2 * N4Q)     { src = k; dst = g_kh; scale = 1.0f; i -= N4Q; }
    else if (i < 3 * N4Q)     { src = v; dst = g_vh; scale = 1.0f; i -= 2 * N4Q; }
    else                      { src = m; dst = g_mh; scale = 1.4426950408889634f;
                                i -= 3 * N4Q; if (i >= N4M) return; }
    float4 f = ((const float4*)src)[i];
    __half2 h0 = __floats2half2_rn(f.x * scale, f.y * scale);
    __half2 h1 = __floats2half2_rn(f.z * scale, f.w * scale);
    ((__half2*)dst)[2 * i]     = h0;
    ((__half2*)dst)[2 * i + 1] = h1;
}

// ---------------- PTX helpers ----------------
__device__ __forceinline__ float ex2f(float x) {
    float y; asm("ex2.approx.ftz.f32 %0, %1;" : "=f"(y) : "f"(x)); return y;
}
__device__ __forceinline__ void ldsm_x4(uint32_t* d, uint32_t a) {
    asm volatile("ldmatrix.sync.aligned.m8n8.x4.shared.b16 {%0,%1,%2,%3}, [%4];"
                 : "=r"(d[0]), "=r"(d[1]), "=r"(d[2]), "=r"(d[3]) : "r"(a));
}
__device__ __forceinline__ void ldsm_x4t(uint32_t* d, uint32_t a) {
    asm volatile("ldmatrix.sync.aligned.m8n8.x4.trans.shared.b16 {%0,%1,%2,%3}, [%4];"
                 : "=r"(d[0]), "=r"(d[1]), "=r"(d[2]), "=r"(d[3]) : "r"(a));
}
__device__ __forceinline__ void mma16816(float* c, const uint32_t* a,
                                         uint32_t b0, uint32_t b1) {
    asm volatile(
        "mma.sync.aligned.m16n8k16.row.col.f32.f16.f16.f32 "
        "{%0,%1,%2,%3}, {%4,%5,%6,%7}, {%8,%9}, {%0,%1,%2,%3};"
        : "+f"(c[0]), "+f"(c[1]), "+f"(c[2]), "+f"(c[3])
        : "r"(a[0]), "r"(a[1]), "r"(a[2]), "r"(a[3]), "r"(b0), "r"(b1));
}
#define CP16(dst, src) \
    asm volatile("cp.async.cg.shared.global [%0], [%1], 16;" :: "r"(dst), "l"(src))
#define CP_COMMIT() asm volatile("cp.async.commit_group;" ::: "memory")
#define CP_WAIT(n)  asm volatile("cp.async.wait_group %0;" :: "n"(n) : "memory")

__device__ __forceinline__ uint32_t sw128(uint32_t b) {
    return b ^ ((b >> 3) & 0x70);
}

// SMEM layout (bytes): 2-stage double buffer, 68KB total -> 3 CTAs/SM
#define SM_K(s)  ((s) * 8192)               // 64 x 64 half, SW128
#define SM_V(s)  (16384 + (s) * 8192)       // 64 x 64 half, SW128
#define SM_M(s)  (32768 + (s) * 18432)      // 128 rows x 144B
#define SM_TOTAL 69632

// -------- flash attention: 4 warps x 32 rows, 2x B-fragment reuse --------
__global__ __launch_bounds__(128, 3)
void flash_fwd(float* __restrict__ out) {
    extern __shared__ __align__(1024) char smem[];
    const int tid  = threadIdx.x;
    const int w    = tid >> 5;
    const int lane = tid & 31;
    const int g    = lane >> 2;
    const int tq   = lane & 3;
    const int b    = blockIdx.y;
    const int m0   = blockIdx.x * 128;
    const uint32_t smb = (uint32_t)__cvta_generic_to_shared(smem);

    // Q fragments: 2 m16-tiles x 4 k16-chunks x 4 regs
    uint32_t aq[2][4][4];
#pragma unroll
    for (int mt = 0; mt < 2; mt++) {
        const __half* qb  = g_qh + ((size_t)b * SQ + m0 + w * 32 + mt * 16 + g) * HD;
        const __half* qb8 = qb + 8 * HD;
#pragma unroll
        for (int kt = 0; kt < 4; kt++) {
            int c = kt * 16 + 2 * tq;
            aq[mt][kt][0] = *(const uint32_t*)(qb  + c);
            aq[mt][kt][1] = *(const uint32_t*)(qb8 + c);
            aq[mt][kt][2] = *(const uint32_t*)(qb  + c + 8);
            aq[mt][kt][3] = *(const uint32_t*)(qb8 + c + 8);
        }
    }

    float o[2][8][4];
#pragma unroll
    for (int mt = 0; mt < 2; mt++)
#pragma unroll
        for (int nt = 0; nt < 8; nt++)
#pragma unroll
            for (int i = 0; i < 4; i++) o[mt][nt][i] = 0.f;
    float lr[2][2] = {{0.f, 0.f}, {0.f, 0.f}};

    const __half* gk = g_kh + (size_t)b * SKV * HD;
    const __half* gv = g_vh + (size_t)b * SKV * HD;
    const __half* gm = g_mh + (size_t)m0 * SKV;

    const int r2 = tid >> 3;           // 0..15
    const int c2 = tid & 7;
    auto stage = [&](int t, int s) {
        const int kv0 = t * 64;
        const uint32_t ks = smb + SM_K(s), vs = smb + SM_V(s), ms = smb + SM_M(s);
#pragma unroll
        for (int i = 0; i < 4; i++) {
            int r = r2 + i * 16;
            uint32_t off = sw128(r * 128 + c2 * 16);
            CP16(ks + off, gk + (size_t)(kv0 + r) * HD + c2 * 8);
            CP16(vs + off, gv + (size_t)(kv0 + r) * HD + c2 * 8);
        }
#pragma unroll
        for (int i = 0; i < 8; i++) {
            int r = r2 + i * 16;
            CP16(ms + r * 144 + c2 * 16, gm + (size_t)r * SKV + kv0 + c2 * 8);
        }
        CP_COMMIT();
    };

    stage(0, 0);

    const int l7  = lane & 7;
    const int mc  = lane >> 3;
    const int rvb = l7 + ((lane >> 3) & 1) * 8;
    const int cvb = lane >> 4;

#pragma unroll 1
    for (int t = 0; t < 64; t++) {
        const int s = t & 1;
        CP_WAIT(0);
        __syncthreads();
        if (t < 63) stage(t + 1, s ^ 1);

        const uint32_t ks = smb + SM_K(s), vs = smb + SM_V(s);
        const __half* mbase = (const __half*)(smem + SM_M(s));

#pragma unroll
        for (int kt = 0; kt < 4; kt++) {
            // S init = mask fragments (pre-scaled by log2e)
            float sa[2][2][4];
#pragma unroll
            for (int mt = 0; mt < 2; mt++) {
                const __half* mr0 = mbase + (w * 32 + mt * 16 + g) * 72 + 16 * kt + 2 * tq;
                const __half* mr1 = mr0 + 8 * 72;
#pragma unroll
                for (int nt = 0; nt < 2; nt++) {
                    float2 f0 = __half22float2(*(const __half2*)(mr0 + nt * 8));
                    float2 f1 = __half22float2(*(const __half2*)(mr1 + nt * 8));
                    sa[mt][nt][0] = f0.x; sa[mt][nt][1] = f0.y;
                    sa[mt][nt][2] = f1.x; sa[mt][nt][3] = f1.y;
                }
            }
            // K fragments (shared by both m-tiles)
            const int re = 16 * kt + l7, ro = re + 8;
            uint32_t be0[4], be1[4], bo0[4], bo1[4];
            ldsm_x4(be0, ks + sw128(re * 128 + mc * 16));
            ldsm_x4(be1, ks + sw128(re * 128 + (mc + 4) * 16));
            ldsm_x4(bo0, ks + sw128(ro * 128 + mc * 16));
            ldsm_x4(bo1, ks + sw128(ro * 128 + (mc + 4) * 16));

            // QK^T: 16 MMAs, 4 independent chains, dep spacing 4
#pragma unroll
            for (int k4 = 0; k4 < 4; k4++) {
                const uint32_t* bev = (k4 < 2) ? be0 : be1;
                const uint32_t* bov = (k4 < 2) ? bo0 : bo1;
                const int h2 = (k4 & 1) * 2;
#pragma unroll
                for (int mt = 0; mt < 2; mt++) {
                    mma16816(sa[mt][0], aq[mt][k4], bev[h2], bev[h2 + 1]);
                    mma16816(sa[mt][1], aq[mt][k4], bov[h2], bov[h2 + 1]);
                }
            }

            // P = exp2(S), accumulate l, pack to fp16 A-fragments
            uint32_t pa[2][4];
#pragma unroll
            for (int mt = 0; mt < 2; mt++) {
                float p000 = ex2f(sa[mt][0][0]), p001 = ex2f(sa[mt][0][1]);
                float p002 = ex2f(sa[mt][0][2]), p003 = ex2f(sa[mt][0][3]);
                float p100 = ex2f(sa[mt][1][0]), p101 = ex2f(sa[mt][1][1]);
                float p102 = ex2f(sa[mt][1][2]), p103 = ex2f(sa[mt][1][3]);
                lr[mt][0] += (p000 + p001) + (p100 + p101);
                lr[mt][1] += (p002 + p003) + (p102 + p103);
                __half2 h;
                h = __floats2half2_rn(p000, p001); pa[mt][0] = *(uint32_t*)&h;
                h = __floats2half2_rn(p002, p003); pa[mt][1] = *(uint32_t*)&h;
                h = __floats2half2_rn(p100, p101); pa[mt][2] = *(uint32_t*)&h;
                h = __floats2half2_rn(p102, p103); pa[mt][3] = *(uint32_t*)&h;
            }

            // O += P V : each V fragment feeds 4 MMAs (2 m-tiles x 2 n-tiles)
            const int rv = 16 * kt + rvb;
#pragma unroll
            for (int np = 0; np < 4; np++) {
                uint32_t bv[4];
                ldsm_x4t(bv, vs + sw128(rv * 128 + (2 * np + cvb) * 16));
#pragma unroll
                for (int mt = 0; mt < 2; mt++) {
                    mma16816(o[mt][2 * np],     pa[mt], bv[0], bv[1]);
                    mma16816(o[mt][2 * np + 1], pa[mt], bv[2], bv[3]);
                }
            }
        }
    }

    // epilogue: quad-reduce l, normalize, store
#pragma unroll
    for (int mt = 0; mt < 2; mt++) {
        float l0 = lr[mt][0], l1 = lr[mt][1];
        l0 += __shfl_xor_sync(0xffffffffu, l0, 1);
        l0 += __shfl_xor_sync(0xffffffffu, l0, 2);
        l1 += __shfl_xor_sync(0xffffffffu, l1, 1);
        l1 += __shfl_xor_sync(0xffffffffu, l1, 2);
        const float inv0 = 1.f / l0, inv1 = 1.f / l1;
        float* ob0 = out + ((size_t)b * SQ + m0 + w * 32 + mt * 16 + g) * 64 + 2 * tq;
        float* ob1 = ob0 + 8 * 64;
#pragma unroll
        for (int nt = 0; nt < 8; nt++) {
            *(float2*)(ob0 + nt * 8) =
                make_float2(o[mt][nt][0] * inv0, o[mt][nt][1] * inv0);
            *(float2*)(ob1 + nt * 8) =
                make_float2(o[mt][nt][2] * inv1, o[mt][nt][3] * inv1);
        }
    }
}

// ---------------- launch ----------------
extern "C" void kernel_launch(void* const* d_in, const int* in_sizes, int n_in,
                              void* d_out, int out_size) {
    const float* q = (const float*)d_in[0];
    const float* k = (const float*)d_in[1];
    const float* v = (const float*)d_in[2];
    const float* m = (const float*)d_in[3];

    int total4 = 3 * N4Q + N4M;
    cvt_all<<<(total4 + 255) / 256, 256>>>(q, k, v, m);

    cudaFuncSetAttribute(flash_fwd, cudaFuncAttributeMaxDynamicSharedMemorySize,
                         SM_TOTAL);
    dim3 grid(SQ / 128, NB);
    flash_fwd<<<grid, 128, SM_TOTAL>>>((float*)d_out);
}

// round 17
// speedup vs baseline: 1.1021x; 1.1021x over previous
#include <cuda_runtime.h>
#include <cuda_fp16.h>
#include <cstdint>

#define NB   16
#define SQ   4096
#define SKV  4096
#define HD   64

// ---------------- fp16 staging buffers ----------------
__device__ __half g_qh[(size_t)NB * SQ * HD];    // Q * 0.125*log2e
__device__ __half g_kh[(size_t)NB * SKV * HD];   // K
__device__ __half g_vh[(size_t)NB * SKV * HD];   // V
__device__ __half g_mh[(size_t)SQ * SKV];        // mask * log2e

// ---------------- fused conversion pre-pass ----------------
#define N4Q (NB * SQ * HD / 4)
#define N4M (SQ * SKV / 4)
__global__ void cvt_all(const float* __restrict__ q, const float* __restrict__ k,
                        const float* __restrict__ v, const float* __restrict__ m) {
    int i = blockIdx.x * blockDim.x + threadIdx.x;
    const float* src;
    __half* dst;
    float scale;
    if (i < N4Q)              { src = q; dst = g_qh; scale = 0.18033688011112042f; }
    else if (i < 2 * N4Q)     { src = k; dst = g_kh; scale = 1.0f; i -= N4Q; }
    else if (i < 3 * N4Q)     { src = v; dst = g_vh; scale = 1.0f; i -= 2 * N4Q; }
    else                      { src = m; dst = g_mh; scale = 1.4426950408889634f;
                                i -= 3 * N4Q; if (i >= N4M) return; }
    float4 f = ((const float4*)src)[i];
    __half2 h0 = __floats2half2_rn(f.x * scale, f.y * scale);
    __half2 h1 = __floats2half2_rn(f.z * scale, f.w * scale);
    ((__half2*)dst)[2 * i]     = h0;
    ((__half2*)dst)[2 * i + 1] = h1;
}

// ---------------- PTX helpers ----------------
__device__ __forceinline__ float ex2f(float x) {
    float y; asm("ex2.approx.ftz.f32 %0, %1;" : "=f"(y) : "f"(x)); return y;
}
__device__ __forceinline__ void ldsm_x4(uint32_t* d, uint32_t a) {
    asm volatile("ldmatrix.sync.aligned.m8n8.x4.shared.b16 {%0,%1,%2,%3}, [%4];"
                 : "=r"(d[0]), "=r"(d[1]), "=r"(d[2]), "=r"(d[3]) : "r"(a));
}
__device__ __forceinline__ void ldsm_x4t(uint32_t* d, uint32_t a) {
    asm volatile("ldmatrix.sync.aligned.m8n8.x4.trans.shared.b16 {%0,%1,%2,%3}, [%4];"
                 : "=r"(d[0]), "=r"(d[1]), "=r"(d[2]), "=r"(d[3]) : "r"(a));
}
__device__ __forceinline__ void mma16816(float* c, const uint32_t* a,
                                         uint32_t b0, uint32_t b1) {
    asm volatile(
        "mma.sync.aligned.m16n8k16.row.col.f32.f16.f16.f32 "
        "{%0,%1,%2,%3}, {%4,%5,%6,%7}, {%8,%9}, {%0,%1,%2,%3};"
        : "+f"(c[0]), "+f"(c[1]), "+f"(c[2]), "+f"(c[3])
        : "r"(a[0]), "r"(a[1]), "r"(a[2]), "r"(a[3]), "r"(b0), "r"(b1));
}
#define CP16(dst, src) \
    asm volatile("cp.async.cg.shared.global [%0], [%1], 16;" :: "r"(dst), "l"(src))
#define CP_COMMIT() asm volatile("cp.async.commit_group;" ::: "memory")
#define CP_WAIT(n)  asm volatile("cp.async.wait_group %0;" :: "n"(n) : "memory")

__device__ __forceinline__ uint32_t sw128(uint32_t b) {
    return b ^ ((b >> 3) & 0x70);
}

// SMEM layout (bytes): 2-stage double buffer
#define SM_K(s)  ((s) * 8192)               // 64 x 64 half, SW128
#define SM_V(s)  (16384 + (s) * 8192)       // 64 x 64 half, SW128
#define SM_M(s)  (32768 + (s) * 18432)      // 128 rows x 144B
#define SM_TOTAL 69632

// -------- flash attention: 4 warps x 32 rows, QK pipelined 1 kt ahead --------
__global__ __launch_bounds__(128, 2)
void flash_fwd(float* __restrict__ out) {
    extern __shared__ __align__(1024) char smem[];
    const int tid  = threadIdx.x;
    const int w    = tid >> 5;
    const int lane = tid & 31;
    const int g    = lane >> 2;
    const int tq   = lane & 3;
    const int b    = blockIdx.y;
    const int m0   = blockIdx.x * 128;
    const uint32_t smb = (uint32_t)__cvta_generic_to_shared(smem);

    // Q fragments: 2 m16-tiles x 4 k16-chunks x 4 regs
    uint32_t aq[2][4][4];
#pragma unroll
    for (int mt = 0; mt < 2; mt++) {
        const __half* qb  = g_qh + ((size_t)b * SQ + m0 + w * 32 + mt * 16 + g) * HD;
        const __half* qb8 = qb + 8 * HD;
#pragma unroll
        for (int kt = 0; kt < 4; kt++) {
            int c = kt * 16 + 2 * tq;
            aq[mt][kt][0] = *(const uint32_t*)(qb  + c);
            aq[mt][kt][1] = *(const uint32_t*)(qb8 + c);
            aq[mt][kt][2] = *(const uint32_t*)(qb  + c + 8);
            aq[mt][kt][3] = *(const uint32_t*)(qb8 + c + 8);
        }
    }

    float o[2][8][4];
#pragma unroll
    for (int mt = 0; mt < 2; mt++)
#pragma unroll
        for (int nt = 0; nt < 8; nt++)
#pragma unroll
            for (int i = 0; i < 4; i++) o[mt][nt][i] = 0.f;
    float lr[2][2] = {{0.f, 0.f}, {0.f, 0.f}};

    const __half* gk = g_kh + (size_t)b * SKV * HD;
    const __half* gv = g_vh + (size_t)b * SKV * HD;
    const __half* gm = g_mh + (size_t)m0 * SKV;

    const int r2 = tid >> 3;           // 0..15
    const int c2 = tid & 7;
    auto stage = [&](int t, int s) {
        const int kv0 = t * 64;
        const uint32_t ks = smb + SM_K(s), vs = smb + SM_V(s), ms = smb + SM_M(s);
#pragma unroll
        for (int i = 0; i < 4; i++) {
            int r = r2 + i * 16;
            uint32_t off = sw128(r * 128 + c2 * 16);
            CP16(ks + off, gk + (size_t)(kv0 + r) * HD + c2 * 8);
            CP16(vs + off, gv + (size_t)(kv0 + r) * HD + c2 * 8);
        }
#pragma unroll
        for (int i = 0; i < 8; i++) {
            int r = r2 + i * 16;
            CP16(ms + r * 144 + c2 * 16, gm + (size_t)r * SKV + kv0 + c2 * 8);
        }
        CP_COMMIT();
    };

    stage(0, 0);

    const int l7  = lane & 7;
    const int mc  = lane >> 3;
    const int rvb = l7 + ((lane >> 3) & 1) * 8;
    const int cvb = lane >> 4;

#pragma unroll 1
    for (int t = 0; t < 64; t++) {
        const int s = t & 1;
        CP_WAIT(0);
        __syncthreads();
        if (t < 63) stage(t + 1, s ^ 1);

        const uint32_t ks = smb + SM_K(s), vs = smb + SM_V(s);
        const __half* mbase = (const __half*)(smem + SM_M(s));

        // S ping-pong: [buf][mt][nt][4]
        float sa[2][2][2][4];

        // mask init for kt (S accumulator C-init, pre-scaled by log2e)
        auto load_mask = [&](int kt, float (&sx)[2][2][4]) {
#pragma unroll
            for (int mt = 0; mt < 2; mt++) {
                const __half* mr0 =
                    mbase + (w * 32 + mt * 16 + g) * 72 + 16 * kt + 2 * tq;
                const __half* mr1 = mr0 + 8 * 72;
#pragma unroll
                for (int nt = 0; nt < 2; nt++) {
                    float2 f0 = __half22float2(*(const __half2*)(mr0 + nt * 8));
                    float2 f1 = __half22float2(*(const __half2*)(mr1 + nt * 8));
                    sx[mt][nt][0] = f0.x; sx[mt][nt][1] = f0.y;
                    sx[mt][nt][2] = f1.x; sx[mt][nt][3] = f1.y;
                }
            }
        };
        // QK^T for kt: 16 MMAs into sx
        auto do_qk = [&](int kt, float (&sx)[2][2][4]) {
            const int re = 16 * kt + l7, ro = re + 8;
            uint32_t be0[4], be1[4], bo0[4], bo1[4];
            ldsm_x4(be0, ks + sw128(re * 128 + mc * 16));
            ldsm_x4(be1, ks + sw128(re * 128 + (mc + 4) * 16));
            ldsm_x4(bo0, ks + sw128(ro * 128 + mc * 16));
            ldsm_x4(bo1, ks + sw128(ro * 128 + (mc + 4) * 16));
#pragma unroll
            for (int k4 = 0; k4 < 4; k4++) {
                const uint32_t* bev = (k4 < 2) ? be0 : be1;
                const uint32_t* bov = (k4 < 2) ? bo0 : bo1;
                const int h2 = (k4 & 1) * 2;
#pragma unroll
                for (int mt = 0; mt < 2; mt++) {
                    mma16816(sx[mt][0], aq[mt][k4], bev[h2], bev[h2 + 1]);
                    mma16816(sx[mt][1], aq[mt][k4], bov[h2], bov[h2 + 1]);
                }
            }
        };

        load_mask(0, sa[0]);
        do_qk(0, sa[0]);

#pragma unroll
        for (int kt = 0; kt < 4; kt++) {
            const int cur = kt & 1;
            // issue next kt's QK (independent tensor + LDS work) BEFORE
            // consuming this kt's S — hides HMMA result latency
            if (kt < 3) {
                load_mask(kt + 1, sa[cur ^ 1]);
                do_qk(kt + 1, sa[cur ^ 1]);
            }

            // P = exp2(S), accumulate l, pack to fp16 A-fragments
            uint32_t pa[2][4];
#pragma unroll
            for (int mt = 0; mt < 2; mt++) {
                float p000 = ex2f(sa[cur][mt][0][0]), p001 = ex2f(sa[cur][mt][0][1]);
                float p002 = ex2f(sa[cur][mt][0][2]), p003 = ex2f(sa[cur][mt][0][3]);
                float p100 = ex2f(sa[cur][mt][1][0]), p101 = ex2f(sa[cur][mt][1][1]);
                float p102 = ex2f(sa[cur][mt][1][2]), p103 = ex2f(sa[cur][mt][1][3]);
                lr[mt][0] += (p000 + p001) + (p100 + p101);
                lr[mt][1] += (p002 + p003) + (p102 + p103);
                __half2 h;
                h = __floats2half2_rn(p000, p001); pa[mt][0] = *(uint32_t*)&h;
                h = __floats2half2_rn(p002, p003); pa[mt][1] = *(uint32_t*)&h;
                h = __floats2half2_rn(p100, p101); pa[mt][2] = *(uint32_t*)&h;
                h = __floats2half2_rn(p102, p103); pa[mt][3] = *(uint32_t*)&h;
            }

            // O += P V
            const int rv = 16 * kt + rvb;
#pragma unroll
            for (int np = 0; np < 4; np++) {
                uint32_t bv[4];
                ldsm_x4t(bv, vs + sw128(rv * 128 + (2 * np + cvb) * 16));
#pragma unroll
                for (int mt = 0; mt < 2; mt++) {
                    mma16816(o[mt][2 * np],     pa[mt], bv[0], bv[1]);
                    mma16816(o[mt][2 * np + 1], pa[mt], bv[2], bv[3]);
                }
            }
        }
    }

    // epilogue: quad-reduce l, normalize, store
#pragma unroll
    for (int mt = 0; mt < 2; mt++) {
        float l0 = lr[mt][0], l1 = lr[mt][1];
        l0 += __shfl_xor_sync(0xffffffffu, l0, 1);
        l0 += __shfl_xor_sync(0xffffffffu, l0, 2);
        l1 += __shfl_xor_sync(0xffffffffu, l1, 1);
        l1 += __shfl_xor_sync(0xffffffffu, l1, 2);
        const float inv0 = 1.f / l0, inv1 = 1.f / l1;
        float* ob0 = out + ((size_t)b * SQ + m0 + w * 32 + mt * 16 + g) * 64 + 2 * tq;
        float* ob1 = ob0 + 8 * 64;
#pragma unroll
        for (int nt = 0; nt < 8; nt++) {
            *(float2*)(ob0 + nt * 8) =
                make_float2(o[mt][nt][0] * inv0, o[mt][nt][1] * inv0);
            *(float2*)(ob1 + nt * 8) =
                make_float2(o[mt][nt][2] * inv1, o[mt][nt][3] * inv1);
        }
    }
}

// ---------------- launch ----------------
extern "C" void kernel_launch(void* const* d_in, const int* in_sizes, int n_in,
                              void* d_out, int out_size) {
    const float* q = (const float*)d_in[0];
    const float* k = (const float*)d_in[1];
    const float* v = (const float*)d_in[2];
    const float* m = (const float*)d_in[3];

    int total4 = 3 * N4Q + N4M;
    cvt_all<<<(total4 + 255) / 256, 256>>>(q, k, v, m);

    cudaFuncSetAttribute(flash_fwd, cudaFuncAttributeMaxDynamicSharedMemorySize,
                         SM_TOTAL);
    dim3 grid(SQ / 128, NB);
    flash_fwd<<<grid, 128, SM_TOTAL>>>((float*)d_out);
}